// round 9
// baseline (speedup 1.0000x reference)
#include <cuda_runtime.h>
#include <cuda_fp16.h>
#include <math.h>
#include <stdint.h>

#define BB 16
#define T 4096
#define C 8
#define F 64
#define KW 11
#define PAD 5
#define L 4096
#define NTILE 32        // T/128 tiles (also L/128)

// ---- device scratch (no allocation allowed) ----
__device__ float g_h[BB * F * T];                              // conv+bn out [B][F][T]
__device__ __half g_sbf[(size_t)BB * NTILE * 128 * 64];        // S tiles [b][tile][t][f] SW128
__device__ __half g_wbf[NTILE * 128 * 64];                     // W hi tiles [ltile][l][f] SW128
__device__ __half g_wlo[NTILE * 128 * 64];                     // W lo tiles
__device__ __half g_pehi[NTILE * 128 * 64];                    // PE hi tiles [ttile][t][f] SW128
__device__ __half g_pelo[NTILE * 128 * 64];                    // PE lo tiles
__device__ float g_part2[(size_t)NTILE * BB * L];              // per-ttile partial shift sums

__device__ __forceinline__ uint32_t smem_u32(const void* p) {
    uint32_t a;
    asm("{ .reg .u64 t; cvta.to.shared.u64 t, %1; cvt.u32.u64 %0, t; }" : "=r"(a) : "l"(p));
    return a;
}
__host__ __device__ __forceinline__ uint32_t sw128(uint32_t off) {
    return off ^ ((off >> 3) & 0x70);
}

// ---------------------------------------------------------------------------
// K0a: PE -> fp16 hi/lo swizzled tiles [ttile][t][f]
// ---------------------------------------------------------------------------
__global__ void peprep_kernel() {
    int idx = blockIdx.x * 256 + threadIdx.x;      // F*T
    int f = idx >> 12, t = idx & (T - 1);
    float ts = powf(1e-4f, (float)(2 * (f >> 1)) / 64.0f);
    float ang = (float)t * ts;
    float v = (f & 1) ? cosf(ang) : sinf(ang);
    __half hi = __float2half(v);
    __half lo = __float2half(v - __half2float(hi));
    int tile = t >> 7, r = t & 127;
    uint32_t off = sw128(r * 128 + f * 2);
    *(__half*)((char*)g_pehi + (size_t)tile * 16384 + off) = hi;
    *(__half*)((char*)g_pelo + (size_t)tile * 16384 + off) = lo;
}

// ---------------------------------------------------------------------------
// K0b: W -> fp16 hi/lo swizzled tiles [ltile][l][f]
// ---------------------------------------------------------------------------
__global__ void wprep_kernel(const float* __restrict__ dw) {
    int idx = blockIdx.x * 256 + threadIdx.x;      // F*L
    int f = idx >> 12, l = idx & (L - 1);
    float v = dw[idx];
    __half hi = __float2half(v);
    __half lo = __float2half(v - __half2float(hi));
    int tile = l >> 7, r = l & 127;
    uint32_t off = sw128(r * 128 + f * 2);
    *(__half*)((char*)g_wbf + (size_t)tile * 16384 + off) = hi;
    *(__half*)((char*)g_wlo + (size_t)tile * 16384 + off) = lo;
}

// ---------------------------------------------------------------------------
// K1: Conv1D(SAME) + BatchNorm -> g_h [B][F][T]
// ---------------------------------------------------------------------------
#define CONV_TT 64
__global__ __launch_bounds__(256) void conv_bn_kernel(
    const float* __restrict__ x, const float* __restrict__ cw,
    const float* __restrict__ cb, const float* __restrict__ gamma,
    const float* __restrict__ beta, const float* __restrict__ mean,
    const float* __restrict__ var)
{
    __shared__ float xs[(CONV_TT + KW - 1) * 9];
    __shared__ float ws[KW * C * F];
    __shared__ float sc[F], bi[F];

    int b = blockIdx.y;
    int t0 = blockIdx.x * CONV_TT;
    int tid = threadIdx.x;

    for (int idx = tid; idx < (CONV_TT + KW - 1) * 9; idx += 256) {
        int i = idx / 9, c = idx % 9;
        float v = 0.f;
        int tg = t0 + i - PAD;
        if (c < 8 && tg >= 0 && tg < T) v = x[(b * T + tg) * C + c];
        xs[idx] = v;
    }
    for (int idx = tid; idx < KW * C * F; idx += 256) ws[idx] = cw[idx];
    if (tid < F) {
        float s = gamma[tid] / sqrtf(var[tid] + 1e-3f);
        sc[tid] = s;
        bi[tid] = (cb[tid] - mean[tid]) * s + beta[tid];
    }
    __syncthreads();

    int tx = tid & 31;
    int ty = tid >> 5;
    float acc0[8], acc1[8];
#pragma unroll
    for (int j = 0; j < 8; j++) { acc0[j] = 0.f; acc1[j] = 0.f; }

#pragma unroll
    for (int k = 0; k < KW; k++) {
#pragma unroll
        for (int c = 0; c < C; c++) {
            float x0 = xs[(tx * 2 + k) * 9 + c];
            float x1 = xs[(tx * 2 + 1 + k) * 9 + c];
            const float* wrow = &ws[(k * C + c) * F + ty * 8];
#pragma unroll
            for (int j = 0; j < 8; j++) {
                float w = wrow[j];
                acc0[j] += x0 * w;
                acc1[j] += x1 * w;
            }
        }
    }
#pragma unroll
    for (int j = 0; j < 8; j++) {
        int f = ty * 8 + j;
        float s = sc[f], o = bi[f];
        float2 v;
        v.x = acc0[j] * s + o;
        v.y = acc1[j] * s + o;
        *(float2*)&g_h[(size_t)(b * F + f) * T + t0 + tx * 2] = v;
    }
}

// ---------------------------------------------------------------------------
// K2: softmax over T, in-place fp32 into g_h
// ---------------------------------------------------------------------------
__global__ __launch_bounds__(256) void softmax_kernel()
{
    int r = blockIdx.x;            // b*F + f
    float* row = g_h + (size_t)r * T;
    int tid = threadIdx.x;

    float v[16];
#pragma unroll
    for (int i = 0; i < 16; i++) v[i] = row[i * 256 + tid];

    float m = v[0];
#pragma unroll
    for (int i = 1; i < 16; i++) m = fmaxf(m, v[i]);

    __shared__ float sm[8], ss[8];
#pragma unroll
    for (int o = 16; o > 0; o >>= 1) m = fmaxf(m, __shfl_xor_sync(~0u, m, o));
    if ((tid & 31) == 0) sm[tid >> 5] = m;
    __syncthreads();
    m = sm[0];
#pragma unroll
    for (int w = 1; w < 8; w++) m = fmaxf(m, sm[w]);

    float e[16];
    float lsum = 0.f;
#pragma unroll
    for (int i = 0; i < 16; i++) { e[i] = expf(v[i] - m); lsum += e[i]; }
#pragma unroll
    for (int o = 16; o > 0; o >>= 1) lsum += __shfl_xor_sync(~0u, lsum, o);
    if ((tid & 31) == 0) ss[tid >> 5] = lsum;
    __syncthreads();
    float total = 0.f;
#pragma unroll
    for (int w = 0; w < 8; w++) total += ss[w];

    float inv = 1.f / total;
#pragma unroll
    for (int i = 0; i < 16; i++) row[i * 256 + tid] = e[i] * inv;
}

// ---------------------------------------------------------------------------
// K2b: transpose S -> fp16 swizzled tiles g_sbf[b][tile][t][f]
// ---------------------------------------------------------------------------
__global__ __launch_bounds__(256) void strans_kernel()
{
    __shared__ float st[64][130];
    int b = blockIdx.y;
    int tile = blockIdx.x;
    int tid = threadIdx.x;
    const float* src = g_h + (size_t)b * F * T + tile * 128;

#pragma unroll
    for (int it = 0; it < 8; it++) {
        int e = tid + it * 256;        // f = e/32, t4 = e%32
        int f = e >> 5, t4 = e & 31;
        float4 v = *(const float4*)(src + (size_t)f * T + t4 * 4);
        st[f][t4 * 4 + 0] = v.x; st[f][t4 * 4 + 1] = v.y;
        st[f][t4 * 4 + 2] = v.z; st[f][t4 * 4 + 3] = v.w;
    }
    __syncthreads();

    char* dst = (char*)g_sbf + ((size_t)b * NTILE + tile) * 16384;
#pragma unroll
    for (int it = 0; it < 4; it++) {
        int e = tid + it * 256;        // t = e>>3, fc = e&7
        int t = e >> 3, fc = e & 7;
        __half tmp[8];
#pragma unroll
        for (int j = 0; j < 8; j++) tmp[j] = __float2half(st[fc * 8 + j][t]);
        *(float4*)(dst + sw128(t * 128 + fc * 16)) = *(float4*)tmp;
    }
}

// ---------------------------------------------------------------------------
// K3: fused HMMA: c_init = PEhi@Whi + PElo@Whi + PEhi@Wlo + bias (registers),
// then per b: c = c_init + S@Whi + S@Wlo; quad-merged sigmoid; t-sum
// CTA = (ltile, ttile): 128 l x 128 t x 16 b; 256 threads = 8 warps (2tq x 4lq)
// ---------------------------------------------------------------------------
__device__ __forceinline__ void ldsm4(uint32_t* r, uint32_t addr) {
    asm volatile("ldmatrix.sync.aligned.m8n8.x4.shared.b16 {%0,%1,%2,%3}, [%4];"
                 : "=r"(r[0]), "=r"(r[1]), "=r"(r[2]), "=r"(r[3]) : "r"(addr));
}
__device__ __forceinline__ void mma16816(float* c, const uint32_t* a, const uint32_t* b) {
    asm volatile(
        "mma.sync.aligned.m16n8k16.row.col.f32.f16.f16.f32 "
        "{%0,%1,%2,%3}, {%4,%5,%6,%7}, {%8,%9}, {%0,%1,%2,%3};"
        : "+f"(c[0]), "+f"(c[1]), "+f"(c[2]), "+f"(c[3])
        : "r"(a[0]), "r"(a[1]), "r"(a[2]), "r"(a[3]), "r"(b[0]), "r"(b[1]));
}

extern __shared__ __align__(16) unsigned char g_smem[];

// smem regions (16KB each): R0=Whi  R1=Wlo (reduce scratch later)  R2/R3=S dbl buf
#define R0 0
#define R1 16384
#define R2 32768
#define R3 49152
#define HMMA_SMEM 65536

__global__ __launch_bounds__(256) void hmma_sig_kernel(const float* __restrict__ db)
{
    unsigned char* dsm = g_smem;
    int ltile = blockIdx.x, ttile = blockIdx.y;
    int l0 = ltile * 128;
    int tid = threadIdx.x, lane = tid & 31, w = tid >> 5;
    int tq = w >> 2, lq = w & 3;

    // load Whi, Wlo, PEhi(R2), PElo(R3)
    {
        const float4* s;
        float4* d;
        s = (const float4*)((const char*)g_wbf + (size_t)ltile * 16384);
        d = (float4*)(dsm + R0);
#pragma unroll
        for (int i = 0; i < 4; i++) d[tid + i * 256] = s[tid + i * 256];
        s = (const float4*)((const char*)g_wlo + (size_t)ltile * 16384);
        d = (float4*)(dsm + R1);
#pragma unroll
        for (int i = 0; i < 4; i++) d[tid + i * 256] = s[tid + i * 256];
        s = (const float4*)((const char*)g_pehi + (size_t)ttile * 16384);
        d = (float4*)(dsm + R2);
#pragma unroll
        for (int i = 0; i < 4; i++) d[tid + i * 256] = s[tid + i * 256];
        s = (const float4*)((const char*)g_pelo + (size_t)ttile * 16384);
        d = (float4*)(dsm + R3);
#pragma unroll
        for (int i = 0; i < 4; i++) d[tid + i * 256] = s[tid + i * 256];
    }
    __syncthreads();

    uint32_t base = smem_u32(dsm);

    // B fragments (W hi and lo)
    uint32_t Bfh[4][4][2], Bfl[4][4][2];
    {
        int grp = lane >> 3;
        int nrow = lq * 32 + ((grp & 2) << 2) + (lane & 7);
        int kh = grp & 1;
#pragma unroll
        for (int p = 0; p < 2; p++) {
#pragma unroll
            for (int k = 0; k < 4; k++) {
                uint32_t off = sw128((uint32_t)(nrow + p * 16) * 128 + k * 32 + kh * 16);
                uint32_t r[4];
                ldsm4(r, base + R0 + off);
                Bfh[2 * p][k][0] = r[0];     Bfh[2 * p][k][1] = r[1];
                Bfh[2 * p + 1][k][0] = r[2]; Bfh[2 * p + 1][k][1] = r[3];
                ldsm4(r, base + R1 + off);
                Bfl[2 * p][k][0] = r[0];     Bfl[2 * p][k][1] = r[1];
                Bfl[2 * p + 1][k][0] = r[2]; Bfl[2 * p + 1][k][1] = r[3];
            }
        }
    }

    int arow = lane & 15;
    int akh = lane >> 4;

    // bias values for this thread's 8 l columns
    float breg[8];
#pragma unroll
    for (int nf = 0; nf < 4; nf++) {
        breg[nf * 2 + 0] = db[l0 + lq * 32 + nf * 8 + (lane & 3) * 2 + 0];
        breg[nf * 2 + 1] = db[l0 + lq * 32 + nf * 8 + (lane & 3) * 2 + 1];
    }

    // c_init = PEhi@Whi + PElo@Whi + PEhi@Wlo + bias  (64 regs)
    float cinit[4][4][4];
#pragma unroll
    for (int tf = 0; tf < 4; tf++) {
        int row = tq * 64 + tf * 16 + arow;
        uint32_t Ah[4][4], Al[4][4];
#pragma unroll
        for (int k = 0; k < 4; k++) {
            uint32_t off = sw128((uint32_t)row * 128 + k * 32 + akh * 16);
            ldsm4(Ah[k], base + R2 + off);
            ldsm4(Al[k], base + R3 + off);
        }
        float c[4][4];
#pragma unroll
        for (int nf = 0; nf < 4; nf++)
#pragma unroll
            for (int q = 0; q < 4; q++) c[nf][q] = 0.f;
#pragma unroll
        for (int k = 0; k < 4; k++)
#pragma unroll
            for (int nf = 0; nf < 4; nf++) {
                mma16816(c[nf], Ah[k], Bfh[nf][k]);
                mma16816(c[nf], Al[k], Bfh[nf][k]);
                mma16816(c[nf], Ah[k], Bfl[nf][k]);
            }
#pragma unroll
        for (int nf = 0; nf < 4; nf++) {
            cinit[tf][nf][0] = c[nf][0] + breg[nf * 2 + 0];
            cinit[tf][nf][1] = c[nf][1] + breg[nf * 2 + 1];
            cinit[tf][nf][2] = c[nf][2] + breg[nf * 2 + 0];
            cinit[tf][nf][3] = c[nf][3] + breg[nf * 2 + 1];
        }
    }
    __syncthreads();   // done reading R2/R3 (PE tiles)

    // load S(b=0) into R2
    const char* sbase0 = (const char*)g_sbf + (size_t)ttile * 16384;
    {
        const float4* s = (const float4*)sbase0;   // b=0
        float4* d = (float4*)(dsm + R2);
#pragma unroll
        for (int i = 0; i < 4; i++) d[tid + i * 256] = s[tid + i * 256];
    }
    __syncthreads();

    float* red = (float*)(dsm + R1);

    for (int b = 0; b < BB; b++) {
        int cur = b & 1;
        uint32_t sA = base + (cur ? R3 : R2);

        // prefetch next S tile into registers
        float4 creg[4];
        if (b + 1 < BB) {
            const float4* s =
                (const float4*)(sbase0 + (size_t)(b + 1) * NTILE * 16384);
#pragma unroll
            for (int j = 0; j < 4; j++) creg[j] = s[tid + j * 256];
        }

        float dacc[8];
#pragma unroll
        for (int j = 0; j < 8; j++) dacc[j] = 0.f;

        // process tf in pairs so quads group 4 same-column elements
#pragma unroll
        for (int tfp = 0; tfp < 2; tfp++) {
            int tfA = tfp * 2, tfB = tfp * 2 + 1;
            int rowA = tq * 64 + tfA * 16 + arow;
            int rowB = rowA + 16;

            float cA[4][4], cB[4][4];
#pragma unroll
            for (int nf = 0; nf < 4; nf++)
#pragma unroll
                for (int q = 0; q < 4; q++) {
                    cA[nf][q] = cinit[tfA][nf][q];
                    cB[nf][q] = cinit[tfB][nf][q];
                }
#pragma unroll
            for (int k = 0; k < 4; k++) {
                uint32_t a0[4], a1[4];
                ldsm4(a0, sA + sw128((uint32_t)rowA * 128 + k * 32 + akh * 16));
                ldsm4(a1, sA + sw128((uint32_t)rowB * 128 + k * 32 + akh * 16));
#pragma unroll
                for (int nf = 0; nf < 4; nf++) {
                    mma16816(cA[nf], a0, Bfh[nf][k]);
                    mma16816(cA[nf], a0, Bfl[nf][k]);
                    mma16816(cB[nf], a1, Bfh[nf][k]);
                    mma16816(cB[nf], a1, Bfl[nf][k]);
                }
            }

            // quad-merged sigmoid: one reciprocal per 4 same-column elements
            // sum 2*sigma over {cA[nf][par], cA[nf][par+2], cB[nf][par], cB[nf][par+2]}
#pragma unroll
            for (int nf = 0; nf < 4; nf++) {
#pragma unroll
                for (int par = 0; par < 2; par++) {
                    float e0 = __expf(-cA[nf][par]);
                    float e1 = __expf(-cA[nf][par + 2]);
                    float e2 = __expf(-cB[nf][par]);
                    float e3 = __expf(-cB[nf][par + 2]);
                    float s01 = e0 + e1, s23 = e2 + e3;
                    float a01 = 1.f + s01, a23 = 1.f + s23;
                    float d01 = fmaf(e0, e1, a01);   // (1+e0)(1+e1)
                    float d23 = fmaf(e2, e3, a23);
                    float n01 = a01 + 1.f;           // 2+e0+e1
                    float n23 = a23 + 1.f;
                    float den = d01 * d23;
                    float num = fmaf(n23, d01, n01 * d23);
                    float r = __fdividef(num, den);  // sig0+sig1+sig2+sig3
                    dacc[nf * 2 + par] += r + r;     // 2*sigma each
                }
            }
        }

        // each slot saw 2 tfp * 4 = 8 elements of 2*sigmoid
#pragma unroll
        for (int j = 0; j < 8; j++) dacc[j] -= 8.f;

        // reduce over the 8 lanes sharing lane&3
#pragma unroll
        for (int o = 4; o < 32; o <<= 1)
#pragma unroll
            for (int j = 0; j < 8; j++) dacc[j] += __shfl_xor_sync(~0u, dacc[j], o);

        // store prefetched S tile
        if (b + 1 < BB) {
            float4* d = (float4*)(dsm + (cur ? R2 : R3));
#pragma unroll
            for (int j = 0; j < 4; j++) d[tid + j * 256] = creg[j];
        }

        if (lane < 4) {
#pragma unroll
            for (int nf = 0; nf < 4; nf++) {
                red[tq * 128 + lq * 32 + nf * 8 + lane * 2 + 0] = dacc[nf * 2 + 0];
                red[tq * 128 + lq * 32 + nf * 8 + lane * 2 + 1] = dacc[nf * 2 + 1];
            }
        }
        __syncthreads();
        if (tid < 128)
            g_part2[((size_t)ttile * BB + b) * L + l0 + tid] = red[tid] + red[128 + tid];
        __syncthreads();
    }
}

// ---------------------------------------------------------------------------
// K4: Gaussian RBF warp — sums 32 ttile partials, truncated window |d| <= 6
// ---------------------------------------------------------------------------
__global__ __launch_bounds__(256) void warp_kernel(
    const float* __restrict__ x, float* __restrict__ out)
{
    int gid = blockIdx.x * 256 + threadIdx.x;   // = b*L + l
    int b = gid >> 12;
    int l = gid & (L - 1);

    float shift = 0.f;
#pragma unroll
    for (int tt = 0; tt < NTILE; tt++) shift += g_part2[(size_t)tt * BB * L + gid];

    float scale = (float)T / (float)L;
    float s = ((float)(l + 1) + shift) * scale;

    const float INV_AMP = (float)(1.0 / 1.772637204826652);
    float acc[8];
#pragma unroll
    for (int c = 0; c < 8; c++) acc[c] = 0.f;

    int lo = (int)ceilf(s - 6.0f);  if (lo < 1) lo = 1;
    int hi = (int)floorf(s + 6.0f); if (hi > T) hi = T;

    const float* xb = x + (size_t)b * T * C;
    for (int t = lo; t <= hi; t++) {
        float dd = (float)t - s;
        float wgt = expf(-dd * dd) * INV_AMP;
        const float4* xr = (const float4*)&xb[(t - 1) * C];
        float4 p0 = xr[0], p1 = xr[1];
        acc[0] += wgt * p0.x; acc[1] += wgt * p0.y;
        acc[2] += wgt * p0.z; acc[3] += wgt * p0.w;
        acc[4] += wgt * p1.x; acc[5] += wgt * p1.y;
        acc[6] += wgt * p1.z; acc[7] += wgt * p1.w;
    }
    float4* o = (float4*)&out[(size_t)gid * C];
    float4 r0 = {acc[0], acc[1], acc[2], acc[3]};
    float4 r1 = {acc[4], acc[5], acc[6], acc[7]};
    o[0] = r0; o[1] = r1;
}

// ---------------------------------------------------------------------------
extern "C" void kernel_launch(void* const* d_in, const int* in_sizes, int n_in,
                              void* d_out, int out_size)
{
    const float* x     = (const float*)d_in[0];
    const float* cw    = (const float*)d_in[1];
    const float* cb    = (const float*)d_in[2];
    const float* gamma = (const float*)d_in[3];
    const float* beta  = (const float*)d_in[4];
    const float* mean  = (const float*)d_in[5];
    const float* var   = (const float*)d_in[6];
    const float* dw    = (const float*)d_in[7];
    const float* db    = (const float*)d_in[8];
    float* out = (float*)d_out;

    cudaFuncSetAttribute(hmma_sig_kernel,
                         cudaFuncAttributeMaxDynamicSharedMemorySize, HMMA_SMEM);

    peprep_kernel<<<(F * T) / 256, 256>>>();
    wprep_kernel<<<(F * L) / 256, 256>>>(dw);
    conv_bn_kernel<<<dim3(T / CONV_TT, BB), 256>>>(x, cw, cb, gamma, beta, mean, var);
    softmax_kernel<<<BB * F, 256>>>();
    strans_kernel<<<dim3(NTILE, BB), 256>>>();
    hmma_sig_kernel<<<dim3(NTILE, NTILE), 256, HMMA_SMEM>>>(db);
    warp_kernel<<<(BB * L) / 256, 256>>>(x, out);
}

// round 11
// speedup vs baseline: 1.2283x; 1.2283x over previous
#include <cuda_runtime.h>
#include <cuda_fp16.h>
#include <math.h>
#include <stdint.h>

#define BB 16
#define T 4096
#define C 8
#define F 64
#define KW 11
#define PAD 5
#define L 4096
#define NTILE 32        // T/128 tiles (also L/128)

// ---- device scratch (no allocation allowed) ----
__device__ float g_h[BB * F * T];                              // conv+bn out [B][F][T]
__device__ __half g_sbf[(size_t)BB * NTILE * 128 * 64];        // S tiles [b][tile][t][f] SW128
__device__ __half g_wbf[NTILE * 128 * 64];                     // W hi tiles [ltile][l][f] SW128
__device__ __half g_wlo[NTILE * 128 * 64];                     // W lo tiles
__device__ __half g_pehi[NTILE * 128 * 64];                    // PE hi tiles [ttile][t][f] SW128
__device__ __half g_pelo[NTILE * 128 * 64];                    // PE lo tiles
__device__ float g_part2[(size_t)NTILE * BB * L];              // per-ttile partial shift sums

__device__ __forceinline__ uint32_t smem_u32(const void* p) {
    uint32_t a;
    asm("{ .reg .u64 t; cvta.to.shared.u64 t, %1; cvt.u32.u64 %0, t; }" : "=r"(a) : "l"(p));
    return a;
}
__host__ __device__ __forceinline__ uint32_t sw128(uint32_t off) {
    return off ^ ((off >> 3) & 0x70);
}

// ---------------------------------------------------------------------------
// K0a: PE -> fp16 hi/lo swizzled tiles [ttile][t][f]
// ---------------------------------------------------------------------------
__global__ void peprep_kernel() {
    int idx = blockIdx.x * 256 + threadIdx.x;      // F*T
    int f = idx >> 12, t = idx & (T - 1);
    float ts = powf(1e-4f, (float)(2 * (f >> 1)) / 64.0f);
    float ang = (float)t * ts;
    float v = (f & 1) ? cosf(ang) : sinf(ang);
    __half hi = __float2half(v);
    __half lo = __float2half(v - __half2float(hi));
    int tile = t >> 7, r = t & 127;
    uint32_t off = sw128(r * 128 + f * 2);
    *(__half*)((char*)g_pehi + (size_t)tile * 16384 + off) = hi;
    *(__half*)((char*)g_pelo + (size_t)tile * 16384 + off) = lo;
}

// ---------------------------------------------------------------------------
// K0b: W -> fp16 hi/lo swizzled tiles [ltile][l][f]
// ---------------------------------------------------------------------------
__global__ void wprep_kernel(const float* __restrict__ dw) {
    int idx = blockIdx.x * 256 + threadIdx.x;      // F*L
    int f = idx >> 12, l = idx & (L - 1);
    float v = dw[idx];
    __half hi = __float2half(v);
    __half lo = __float2half(v - __half2float(hi));
    int tile = l >> 7, r = l & 127;
    uint32_t off = sw128(r * 128 + f * 2);
    *(__half*)((char*)g_wbf + (size_t)tile * 16384 + off) = hi;
    *(__half*)((char*)g_wlo + (size_t)tile * 16384 + off) = lo;
}

// ---------------------------------------------------------------------------
// K1: Conv1D(SAME) + BatchNorm -> g_h [B][F][T]
// ---------------------------------------------------------------------------
#define CONV_TT 64
__global__ __launch_bounds__(256) void conv_bn_kernel(
    const float* __restrict__ x, const float* __restrict__ cw,
    const float* __restrict__ cb, const float* __restrict__ gamma,
    const float* __restrict__ beta, const float* __restrict__ mean,
    const float* __restrict__ var)
{
    __shared__ float xs[(CONV_TT + KW - 1) * 9];
    __shared__ float ws[KW * C * F];
    __shared__ float sc[F], bi[F];

    int b = blockIdx.y;
    int t0 = blockIdx.x * CONV_TT;
    int tid = threadIdx.x;

    for (int idx = tid; idx < (CONV_TT + KW - 1) * 9; idx += 256) {
        int i = idx / 9, c = idx % 9;
        float v = 0.f;
        int tg = t0 + i - PAD;
        if (c < 8 && tg >= 0 && tg < T) v = x[(b * T + tg) * C + c];
        xs[idx] = v;
    }
    for (int idx = tid; idx < KW * C * F; idx += 256) ws[idx] = cw[idx];
    if (tid < F) {
        float s = gamma[tid] / sqrtf(var[tid] + 1e-3f);
        sc[tid] = s;
        bi[tid] = (cb[tid] - mean[tid]) * s + beta[tid];
    }
    __syncthreads();

    int tx = tid & 31;
    int ty = tid >> 5;
    float acc0[8], acc1[8];
#pragma unroll
    for (int j = 0; j < 8; j++) { acc0[j] = 0.f; acc1[j] = 0.f; }

#pragma unroll
    for (int k = 0; k < KW; k++) {
#pragma unroll
        for (int c = 0; c < C; c++) {
            float x0 = xs[(tx * 2 + k) * 9 + c];
            float x1 = xs[(tx * 2 + 1 + k) * 9 + c];
            const float* wrow = &ws[(k * C + c) * F + ty * 8];
#pragma unroll
            for (int j = 0; j < 8; j++) {
                float w = wrow[j];
                acc0[j] += x0 * w;
                acc1[j] += x1 * w;
            }
        }
    }
#pragma unroll
    for (int j = 0; j < 8; j++) {
        int f = ty * 8 + j;
        float s = sc[f], o = bi[f];
        float2 v;
        v.x = acc0[j] * s + o;
        v.y = acc1[j] * s + o;
        *(float2*)&g_h[(size_t)(b * F + f) * T + t0 + tx * 2] = v;
    }
}

// ---------------------------------------------------------------------------
// K2: softmax over T, in-place fp32 into g_h
// ---------------------------------------------------------------------------
__global__ __launch_bounds__(256) void softmax_kernel()
{
    int r = blockIdx.x;            // b*F + f
    float* row = g_h + (size_t)r * T;
    int tid = threadIdx.x;

    float v[16];
#pragma unroll
    for (int i = 0; i < 16; i++) v[i] = row[i * 256 + tid];

    float m = v[0];
#pragma unroll
    for (int i = 1; i < 16; i++) m = fmaxf(m, v[i]);

    __shared__ float sm[8], ss[8];
#pragma unroll
    for (int o = 16; o > 0; o >>= 1) m = fmaxf(m, __shfl_xor_sync(~0u, m, o));
    if ((tid & 31) == 0) sm[tid >> 5] = m;
    __syncthreads();
    m = sm[0];
#pragma unroll
    for (int w = 1; w < 8; w++) m = fmaxf(m, sm[w]);

    float e[16];
    float lsum = 0.f;
#pragma unroll
    for (int i = 0; i < 16; i++) { e[i] = expf(v[i] - m); lsum += e[i]; }
#pragma unroll
    for (int o = 16; o > 0; o >>= 1) lsum += __shfl_xor_sync(~0u, lsum, o);
    if ((tid & 31) == 0) ss[tid >> 5] = lsum;
    __syncthreads();
    float total = 0.f;
#pragma unroll
    for (int w = 0; w < 8; w++) total += ss[w];

    float inv = 1.f / total;
#pragma unroll
    for (int i = 0; i < 16; i++) row[i * 256 + tid] = e[i] * inv;
}

// ---------------------------------------------------------------------------
// K2b: transpose S -> fp16 swizzled tiles g_sbf[b][tile][t][f]
// ---------------------------------------------------------------------------
__global__ __launch_bounds__(256) void strans_kernel()
{
    __shared__ float st[64][130];
    int b = blockIdx.y;
    int tile = blockIdx.x;
    int tid = threadIdx.x;
    const float* src = g_h + (size_t)b * F * T + tile * 128;

#pragma unroll
    for (int it = 0; it < 8; it++) {
        int e = tid + it * 256;        // f = e/32, t4 = e%32
        int f = e >> 5, t4 = e & 31;
        float4 v = *(const float4*)(src + (size_t)f * T + t4 * 4);
        st[f][t4 * 4 + 0] = v.x; st[f][t4 * 4 + 1] = v.y;
        st[f][t4 * 4 + 2] = v.z; st[f][t4 * 4 + 3] = v.w;
    }
    __syncthreads();

    char* dst = (char*)g_sbf + ((size_t)b * NTILE + tile) * 16384;
#pragma unroll
    for (int it = 0; it < 4; it++) {
        int e = tid + it * 256;        // t = e>>3, fc = e&7
        int t = e >> 3, fc = e & 7;
        __half tmp[8];
#pragma unroll
        for (int j = 0; j < 8; j++) tmp[j] = __float2half(st[fc * 8 + j][t]);
        *(float4*)(dst + sw128(t * 128 + fc * 16)) = *(float4*)tmp;
    }
}

// ---------------------------------------------------------------------------
// K3: fused HMMA: c_init = PEhi@Whi + PElo@Whi + PEhi@Wlo + bias (registers),
// then per b: c = c_init + S@Whi; pair-merged sigmoid; t-sum -> g_part2
// CTA = (ltile, ttile): 128 l x 128 t x 16 b; 256 threads = 8 warps (2tq x 4lq)
// ---------------------------------------------------------------------------
__device__ __forceinline__ void ldsm4(uint32_t* r, uint32_t addr) {
    asm volatile("ldmatrix.sync.aligned.m8n8.x4.shared.b16 {%0,%1,%2,%3}, [%4];"
                 : "=r"(r[0]), "=r"(r[1]), "=r"(r[2]), "=r"(r[3]) : "r"(addr));
}
__device__ __forceinline__ void mma16816(float* c, const uint32_t* a, const uint32_t* b) {
    asm volatile(
        "mma.sync.aligned.m16n8k16.row.col.f32.f16.f16.f32 "
        "{%0,%1,%2,%3}, {%4,%5,%6,%7}, {%8,%9}, {%0,%1,%2,%3};"
        : "+f"(c[0]), "+f"(c[1]), "+f"(c[2]), "+f"(c[3])
        : "r"(a[0]), "r"(a[1]), "r"(a[2]), "r"(a[3]), "r"(b[0]), "r"(b[1]));
}

extern __shared__ __align__(16) unsigned char g_smem[];

// smem regions (16KB each): R0=Whi  R1=Wlo (reduce scratch later)  R2/R3=S dbl buf
#define R0 0
#define R1 16384
#define R2 32768
#define R3 49152
#define HMMA_SMEM 65536

__global__ __launch_bounds__(256) void hmma_sig_kernel(const float* __restrict__ db)
{
    unsigned char* dsm = g_smem;
    int ltile = blockIdx.x, ttile = blockIdx.y;
    int l0 = ltile * 128;
    int tid = threadIdx.x, lane = tid & 31, w = tid >> 5;
    int tq = w >> 2, lq = w & 3;

    // load Whi, Wlo, PEhi(R2), PElo(R3)
    {
        const float4* s;
        float4* d;
        s = (const float4*)((const char*)g_wbf + (size_t)ltile * 16384);
        d = (float4*)(dsm + R0);
#pragma unroll
        for (int i = 0; i < 4; i++) d[tid + i * 256] = s[tid + i * 256];
        s = (const float4*)((const char*)g_wlo + (size_t)ltile * 16384);
        d = (float4*)(dsm + R1);
#pragma unroll
        for (int i = 0; i < 4; i++) d[tid + i * 256] = s[tid + i * 256];
        s = (const float4*)((const char*)g_pehi + (size_t)ttile * 16384);
        d = (float4*)(dsm + R2);
#pragma unroll
        for (int i = 0; i < 4; i++) d[tid + i * 256] = s[tid + i * 256];
        s = (const float4*)((const char*)g_pelo + (size_t)ttile * 16384);
        d = (float4*)(dsm + R3);
#pragma unroll
        for (int i = 0; i < 4; i++) d[tid + i * 256] = s[tid + i * 256];
    }
    __syncthreads();

    uint32_t base = smem_u32(dsm);

    // B fragments (W hi; lo only needed for the c_init stage)
    uint32_t Bfh[4][4][2];
    {
        int grp = lane >> 3;
        int nrow = lq * 32 + ((grp & 2) << 2) + (lane & 7);
        int kh = grp & 1;
#pragma unroll
        for (int p = 0; p < 2; p++) {
#pragma unroll
            for (int k = 0; k < 4; k++) {
                uint32_t off = sw128((uint32_t)(nrow + p * 16) * 128 + k * 32 + kh * 16);
                uint32_t r[4];
                ldsm4(r, base + R0 + off);
                Bfh[2 * p][k][0] = r[0];     Bfh[2 * p][k][1] = r[1];
                Bfh[2 * p + 1][k][0] = r[2]; Bfh[2 * p + 1][k][1] = r[3];
            }
        }
    }

    int arow = lane & 15;
    int akh = lane >> 4;

    // bias values for this thread's 8 l columns
    float breg[8];
#pragma unroll
    for (int nf = 0; nf < 4; nf++) {
        breg[nf * 2 + 0] = db[l0 + lq * 32 + nf * 8 + (lane & 3) * 2 + 0];
        breg[nf * 2 + 1] = db[l0 + lq * 32 + nf * 8 + (lane & 3) * 2 + 1];
    }

    // c_init = PEhi@Whi + PElo@Whi + PEhi@Wlo + bias  (64 regs)
    float cinit[4][4][4];
#pragma unroll
    for (int tf = 0; tf < 4; tf++) {
        int row = tq * 64 + tf * 16 + arow;
        uint32_t Ah[4][4], Al[4][4];
#pragma unroll
        for (int k = 0; k < 4; k++) {
            uint32_t off = sw128((uint32_t)row * 128 + k * 32 + akh * 16);
            ldsm4(Ah[k], base + R2 + off);
            ldsm4(Al[k], base + R3 + off);
        }
        float c[4][4];
#pragma unroll
        for (int nf = 0; nf < 4; nf++)
#pragma unroll
            for (int q = 0; q < 4; q++) c[nf][q] = 0.f;

        // Wlo fragments loaded per k-step here (c_init only), avoiding
        // persistent register cost in the b-mainloop
#pragma unroll
        for (int k = 0; k < 4; k++) {
            int grp = lane >> 3;
            int nrow = lq * 32 + ((grp & 2) << 2) + (lane & 7);
            int kh = grp & 1;
#pragma unroll
            for (int p = 0; p < 2; p++) {
                uint32_t off = sw128((uint32_t)(nrow + p * 16) * 128 + k * 32 + kh * 16);
                uint32_t rl[4];
                ldsm4(rl, base + R1 + off);
                uint32_t Bl0[2] = {rl[0], rl[1]};
                uint32_t Bl1[2] = {rl[2], rl[3]};
                mma16816(c[2 * p], Al[k], Bfh[2 * p][k]);
                mma16816(c[2 * p + 1], Al[k], Bfh[2 * p + 1][k]);
                mma16816(c[2 * p], Ah[k], Bl0);
                mma16816(c[2 * p + 1], Ah[k], Bl1);
            }
#pragma unroll
            for (int nf = 0; nf < 4; nf++) mma16816(c[nf], Ah[k], Bfh[nf][k]);
        }
#pragma unroll
        for (int nf = 0; nf < 4; nf++) {
            cinit[tf][nf][0] = c[nf][0] + breg[nf * 2 + 0];
            cinit[tf][nf][1] = c[nf][1] + breg[nf * 2 + 1];
            cinit[tf][nf][2] = c[nf][2] + breg[nf * 2 + 0];
            cinit[tf][nf][3] = c[nf][3] + breg[nf * 2 + 1];
        }
    }
    __syncthreads();   // done reading R2/R3 (PE tiles)

    // load S(b=0) into R2
    const char* sbase0 = (const char*)g_sbf + (size_t)ttile * 16384;
    {
        const float4* s = (const float4*)sbase0;   // b=0
        float4* d = (float4*)(dsm + R2);
#pragma unroll
        for (int i = 0; i < 4; i++) d[tid + i * 256] = s[tid + i * 256];
    }
    __syncthreads();

    float* red = (float*)(dsm + R1);

    for (int b = 0; b < BB; b++) {
        int cur = b & 1;
        uint32_t sA = base + (cur ? R3 : R2);

        // prefetch next S tile into registers
        float4 creg[4];
        if (b + 1 < BB) {
            const float4* s =
                (const float4*)(sbase0 + (size_t)(b + 1) * NTILE * 16384);
#pragma unroll
            for (int j = 0; j < 4; j++) creg[j] = s[tid + j * 256];
        }

        float dacc[8];
#pragma unroll
        for (int j = 0; j < 8; j++) dacc[j] = 0.f;

#pragma unroll
        for (int tf = 0; tf < 4; tf++) {
            int row = tq * 64 + tf * 16 + arow;
            uint32_t Af[4][4];
#pragma unroll
            for (int k = 0; k < 4; k++)
                ldsm4(Af[k], sA + sw128((uint32_t)row * 128 + k * 32 + akh * 16));

            float c[4][4];
#pragma unroll
            for (int nf = 0; nf < 4; nf++)
#pragma unroll
                for (int q = 0; q < 4; q++) c[nf][q] = cinit[tf][nf][q];
#pragma unroll
            for (int k = 0; k < 4; k++)
#pragma unroll
                for (int nf = 0; nf < 4; nf++) mma16816(c[nf], Af[k], Bfh[nf][k]);

            // pair-merged sigmoid: c[nf][q] and c[nf][q+2] share the l column.
            // 2sig(a)+2sig(b) = 2*(2+ea+eb)/(1+ea+eb+ea*eb); one RCP per pair.
#pragma unroll
            for (int nf = 0; nf < 4; nf++) {
#pragma unroll
                for (int par = 0; par < 2; par++) {
                    float e0 = __expf(-c[nf][par]);
                    float e1 = __expf(-c[nf][par + 2]);
                    float s01 = e0 + e1;
                    float den = fmaf(e0, e1, 1.f + s01);
                    float num = 2.f + s01;
                    float r = __fdividef(num, den);
                    dacc[nf * 2 + par] += r + r;   // 2*sigma for both elements
                }
            }
        }

        // each slot saw 4 tf * 2 = 8 elements of 2*sigmoid
#pragma unroll
        for (int j = 0; j < 8; j++) dacc[j] -= 8.f;

        // reduce over the 8 lanes sharing lane&3
#pragma unroll
        for (int o = 4; o < 32; o <<= 1)
#pragma unroll
            for (int j = 0; j < 8; j++) dacc[j] += __shfl_xor_sync(~0u, dacc[j], o);

        // store prefetched S tile
        if (b + 1 < BB) {
            float4* d = (float4*)(dsm + (cur ? R2 : R3));
#pragma unroll
            for (int j = 0; j < 4; j++) d[tid + j * 256] = creg[j];
        }

        if (lane < 4) {
#pragma unroll
            for (int nf = 0; nf < 4; nf++) {
                red[tq * 128 + lq * 32 + nf * 8 + lane * 2 + 0] = dacc[nf * 2 + 0];
                red[tq * 128 + lq * 32 + nf * 8 + lane * 2 + 1] = dacc[nf * 2 + 1];
            }
        }
        __syncthreads();
        if (tid < 128)
            g_part2[((size_t)ttile * BB + b) * L + l0 + tid] = red[tid] + red[128 + tid];
        __syncthreads();
    }
}

// ---------------------------------------------------------------------------
// K4: Gaussian RBF warp — sums 32 ttile partials, truncated window |d| <= 6
// ---------------------------------------------------------------------------
__global__ __launch_bounds__(256) void warp_kernel(
    const float* __restrict__ x, float* __restrict__ out)
{
    int gid = blockIdx.x * 256 + threadIdx.x;   // = b*L + l
    int b = gid >> 12;
    int l = gid & (L - 1);

    float shift = 0.f;
#pragma unroll
    for (int tt = 0; tt < NTILE; tt++) shift += g_part2[(size_t)tt * BB * L + gid];

    float scale = (float)T / (float)L;
    float s = ((float)(l + 1) + shift) * scale;

    const float INV_AMP = (float)(1.0 / 1.772637204826652);
    float acc[8];
#pragma unroll
    for (int c = 0; c < 8; c++) acc[c] = 0.f;

    int lo = (int)ceilf(s - 6.0f);  if (lo < 1) lo = 1;
    int hi = (int)floorf(s + 6.0f); if (hi > T) hi = T;

    const float* xb = x + (size_t)b * T * C;
    for (int t = lo; t <= hi; t++) {
        float dd = (float)t - s;
        float wgt = expf(-dd * dd) * INV_AMP;
        const float4* xr = (const float4*)&xb[(t - 1) * C];
        float4 p0 = xr[0], p1 = xr[1];
        acc[0] += wgt * p0.x; acc[1] += wgt * p0.y;
        acc[2] += wgt * p0.z; acc[3] += wgt * p0.w;
        acc[4] += wgt * p1.x; acc[5] += wgt * p1.y;
        acc[6] += wgt * p1.z; acc[7] += wgt * p1.w;
    }
    float4* o = (float4*)&out[(size_t)gid * C];
    float4 r0 = {acc[0], acc[1], acc[2], acc[3]};
    float4 r1 = {acc[4], acc[5], acc[6], acc[7]};
    o[0] = r0; o[1] = r1;
}

// ---------------------------------------------------------------------------
extern "C" void kernel_launch(void* const* d_in, const int* in_sizes, int n_in,
                              void* d_out, int out_size)
{
    const float* x     = (const float*)d_in[0];
    const float* cw    = (const float*)d_in[1];
    const float* cb    = (const float*)d_in[2];
    const float* gamma = (const float*)d_in[3];
    const float* beta  = (const float*)d_in[4];
    const float* mean  = (const float*)d_in[5];
    const float* var   = (const float*)d_in[6];
    const float* dw    = (const float*)d_in[7];
    const float* db    = (const float*)d_in[8];
    float* out = (float*)d_out;

    cudaFuncSetAttribute(hmma_sig_kernel,
                         cudaFuncAttributeMaxDynamicSharedMemorySize, HMMA_SMEM);

    peprep_kernel<<<(F * T) / 256, 256>>>();
    wprep_kernel<<<(F * L) / 256, 256>>>(dw);
    conv_bn_kernel<<<dim3(T / CONV_TT, BB), 256>>>(x, cw, cb, gamma, beta, mean, var);
    softmax_kernel<<<BB * F, 256>>>();
    strans_kernel<<<dim3(NTILE, BB), 256>>>();
    hmma_sig_kernel<<<dim3(NTILE, NTILE), 256, HMMA_SMEM>>>(db);
    warp_kernel<<<(BB * L) / 256, 256>>>(x, out);
}

// round 12
// speedup vs baseline: 1.2418x; 1.0110x over previous
#include <cuda_runtime.h>
#include <cuda_fp16.h>
#include <math.h>
#include <stdint.h>

#define BB 16
#define T 4096
#define C 8
#define F 64
#define KW 11
#define PAD 5
#define L 4096
#define NTILE 32        // T/128 tiles (also L/128)

// ---- device scratch (no allocation allowed) ----
__device__ float g_h[BB * F * T];                              // conv+bn out [B][F][T]
__device__ __half g_sbf[(size_t)BB * NTILE * 128 * 64];        // S tiles [b][tile][t][f] SW128
__device__ __half g_wbf[NTILE * 128 * 64];                     // W hi tiles [ltile][l][f] SW128
__device__ __half g_wlo[NTILE * 128 * 64];                     // W lo tiles
__device__ __half g_pehi[NTILE * 128 * 64];                    // PE hi tiles [ttile][t][f] SW128
__device__ __half g_pelo[NTILE * 128 * 64];                    // PE lo tiles
__device__ float g_part2[(size_t)NTILE * BB * L];              // per-ttile partial shift sums

__device__ __forceinline__ uint32_t smem_u32(const void* p) {
    uint32_t a;
    asm("{ .reg .u64 t; cvta.to.shared.u64 t, %1; cvt.u32.u64 %0, t; }" : "=r"(a) : "l"(p));
    return a;
}
__host__ __device__ __forceinline__ uint32_t sw128(uint32_t off) {
    return off ^ ((off >> 3) & 0x70);
}

// ---------------------------------------------------------------------------
// K0a: PE -> fp16 hi/lo swizzled tiles [ttile][t][f]
// ---------------------------------------------------------------------------
__global__ void peprep_kernel() {
    int idx = blockIdx.x * 256 + threadIdx.x;      // F*T
    int f = idx >> 12, t = idx & (T - 1);
    float ts = powf(1e-4f, (float)(2 * (f >> 1)) / 64.0f);
    float ang = (float)t * ts;
    float v = (f & 1) ? cosf(ang) : sinf(ang);
    __half hi = __float2half(v);
    __half lo = __float2half(v - __half2float(hi));
    int tile = t >> 7, r = t & 127;
    uint32_t off = sw128(r * 128 + f * 2);
    *(__half*)((char*)g_pehi + (size_t)tile * 16384 + off) = hi;
    *(__half*)((char*)g_pelo + (size_t)tile * 16384 + off) = lo;
}

// ---------------------------------------------------------------------------
// K0b: W -> fp16 hi/lo swizzled tiles [ltile][l][f]
// ---------------------------------------------------------------------------
__global__ void wprep_kernel(const float* __restrict__ dw) {
    int idx = blockIdx.x * 256 + threadIdx.x;      // F*L
    int f = idx >> 12, l = idx & (L - 1);
    float v = dw[idx];
    __half hi = __float2half(v);
    __half lo = __float2half(v - __half2float(hi));
    int tile = l >> 7, r = l & 127;
    uint32_t off = sw128(r * 128 + f * 2);
    *(__half*)((char*)g_wbf + (size_t)tile * 16384 + off) = hi;
    *(__half*)((char*)g_wlo + (size_t)tile * 16384 + off) = lo;
}

// ---------------------------------------------------------------------------
// K1: Conv1D(SAME) + BatchNorm -> g_h [B][F][T]
// ---------------------------------------------------------------------------
#define CONV_TT 64
__global__ __launch_bounds__(256) void conv_bn_kernel(
    const float* __restrict__ x, const float* __restrict__ cw,
    const float* __restrict__ cb, const float* __restrict__ gamma,
    const float* __restrict__ beta, const float* __restrict__ mean,
    const float* __restrict__ var)
{
    __shared__ float xs[(CONV_TT + KW - 1) * 9];
    __shared__ float ws[KW * C * F];
    __shared__ float sc[F], bi[F];

    int b = blockIdx.y;
    int t0 = blockIdx.x * CONV_TT;
    int tid = threadIdx.x;

    for (int idx = tid; idx < (CONV_TT + KW - 1) * 9; idx += 256) {
        int i = idx / 9, c = idx % 9;
        float v = 0.f;
        int tg = t0 + i - PAD;
        if (c < 8 && tg >= 0 && tg < T) v = x[(b * T + tg) * C + c];
        xs[idx] = v;
    }
    for (int idx = tid; idx < KW * C * F; idx += 256) ws[idx] = cw[idx];
    if (tid < F) {
        float s = gamma[tid] / sqrtf(var[tid] + 1e-3f);
        sc[tid] = s;
        bi[tid] = (cb[tid] - mean[tid]) * s + beta[tid];
    }
    __syncthreads();

    int tx = tid & 31;
    int ty = tid >> 5;
    float acc0[8], acc1[8];
#pragma unroll
    for (int j = 0; j < 8; j++) { acc0[j] = 0.f; acc1[j] = 0.f; }

#pragma unroll
    for (int k = 0; k < KW; k++) {
#pragma unroll
        for (int c = 0; c < C; c++) {
            float x0 = xs[(tx * 2 + k) * 9 + c];
            float x1 = xs[(tx * 2 + 1 + k) * 9 + c];
            const float* wrow = &ws[(k * C + c) * F + ty * 8];
#pragma unroll
            for (int j = 0; j < 8; j++) {
                float w = wrow[j];
                acc0[j] += x0 * w;
                acc1[j] += x1 * w;
            }
        }
    }
#pragma unroll
    for (int j = 0; j < 8; j++) {
        int f = ty * 8 + j;
        float s = sc[f], o = bi[f];
        float2 v;
        v.x = acc0[j] * s + o;
        v.y = acc1[j] * s + o;
        *(float2*)&g_h[(size_t)(b * F + f) * T + t0 + tx * 2] = v;
    }
}

// ---------------------------------------------------------------------------
// K2: softmax over T, in-place fp32 into g_h
// ---------------------------------------------------------------------------
__global__ __launch_bounds__(256) void softmax_kernel()
{
    int r = blockIdx.x;            // b*F + f
    float* row = g_h + (size_t)r * T;
    int tid = threadIdx.x;

    float v[16];
#pragma unroll
    for (int i = 0; i < 16; i++) v[i] = row[i * 256 + tid];

    float m = v[0];
#pragma unroll
    for (int i = 1; i < 16; i++) m = fmaxf(m, v[i]);

    __shared__ float sm[8], ss[8];
#pragma unroll
    for (int o = 16; o > 0; o >>= 1) m = fmaxf(m, __shfl_xor_sync(~0u, m, o));
    if ((tid & 31) == 0) sm[tid >> 5] = m;
    __syncthreads();
    m = sm[0];
#pragma unroll
    for (int w = 1; w < 8; w++) m = fmaxf(m, sm[w]);

    float e[16];
    float lsum = 0.f;
#pragma unroll
    for (int i = 0; i < 16; i++) { e[i] = expf(v[i] - m); lsum += e[i]; }
#pragma unroll
    for (int o = 16; o > 0; o >>= 1) lsum += __shfl_xor_sync(~0u, lsum, o);
    if ((tid & 31) == 0) ss[tid >> 5] = lsum;
    __syncthreads();
    float total = 0.f;
#pragma unroll
    for (int w = 0; w < 8; w++) total += ss[w];

    float inv = 1.f / total;
#pragma unroll
    for (int i = 0; i < 16; i++) row[i * 256 + tid] = e[i] * inv;
}

// ---------------------------------------------------------------------------
// K2b: transpose S -> fp16 swizzled tiles g_sbf[b][tile][t][f]
// ---------------------------------------------------------------------------
__global__ __launch_bounds__(256) void strans_kernel()
{
    __shared__ float st[64][130];
    int b = blockIdx.y;
    int tile = blockIdx.x;
    int tid = threadIdx.x;
    const float* src = g_h + (size_t)b * F * T + tile * 128;

#pragma unroll
    for (int it = 0; it < 8; it++) {
        int e = tid + it * 256;        // f = e/32, t4 = e%32
        int f = e >> 5, t4 = e & 31;
        float4 v = *(const float4*)(src + (size_t)f * T + t4 * 4);
        st[f][t4 * 4 + 0] = v.x; st[f][t4 * 4 + 1] = v.y;
        st[f][t4 * 4 + 2] = v.z; st[f][t4 * 4 + 3] = v.w;
    }
    __syncthreads();

    char* dst = (char*)g_sbf + ((size_t)b * NTILE + tile) * 16384;
#pragma unroll
    for (int it = 0; it < 4; it++) {
        int e = tid + it * 256;        // t = e>>3, fc = e&7
        int t = e >> 3, fc = e & 7;
        __half tmp[8];
#pragma unroll
        for (int j = 0; j < 8; j++) tmp[j] = __float2half(st[fc * 8 + j][t]);
        *(float4*)(dst + sw128(t * 128 + fc * 16)) = *(float4*)tmp;
    }
}

// ---------------------------------------------------------------------------
// K3: fused HMMA, 512 threads = 16 warps (2 tq x 8 lq), each warp nf=2.
// c_init = PEhi@Whi + PElo@Whi + PEhi@Wlo + bias (32 regs), then per b:
// c = c_init + S@Whi; pair-merged sigmoid; t-sum -> g_part2
// ---------------------------------------------------------------------------
__device__ __forceinline__ void ldsm4(uint32_t* r, uint32_t addr) {
    asm volatile("ldmatrix.sync.aligned.m8n8.x4.shared.b16 {%0,%1,%2,%3}, [%4];"
                 : "=r"(r[0]), "=r"(r[1]), "=r"(r[2]), "=r"(r[3]) : "r"(addr));
}
__device__ __forceinline__ void mma16816(float* c, const uint32_t* a, const uint32_t* b) {
    asm volatile(
        "mma.sync.aligned.m16n8k16.row.col.f32.f16.f16.f32 "
        "{%0,%1,%2,%3}, {%4,%5,%6,%7}, {%8,%9}, {%0,%1,%2,%3};"
        : "+f"(c[0]), "+f"(c[1]), "+f"(c[2]), "+f"(c[3])
        : "r"(a[0]), "r"(a[1]), "r"(a[2]), "r"(a[3]), "r"(b[0]), "r"(b[1]));
}

extern __shared__ __align__(16) unsigned char g_smem[];

// smem regions (16KB each): R0=Whi  R1=Wlo (reduce scratch later)  R2/R3=S dbl buf
#define R0 0
#define R1 16384
#define R2 32768
#define R3 49152
#define HMMA_SMEM 65536
#define HT 512

__global__ __launch_bounds__(HT) void hmma_sig_kernel(const float* __restrict__ db)
{
    unsigned char* dsm = g_smem;
    int ltile = blockIdx.x, ttile = blockIdx.y;
    int l0 = ltile * 128;
    int tid = threadIdx.x, lane = tid & 31, w = tid >> 5;
    int tq = w >> 3, lq = w & 7;          // 2 t-groups x 8 l-groups (16 l each)

    // load Whi, Wlo, PEhi(R2), PElo(R3): each 1024 float4
    {
        const float4* s;
        float4* d;
        s = (const float4*)((const char*)g_wbf + (size_t)ltile * 16384);
        d = (float4*)(dsm + R0);
#pragma unroll
        for (int i = 0; i < 2; i++) d[tid + i * HT] = s[tid + i * HT];
        s = (const float4*)((const char*)g_wlo + (size_t)ltile * 16384);
        d = (float4*)(dsm + R1);
#pragma unroll
        for (int i = 0; i < 2; i++) d[tid + i * HT] = s[tid + i * HT];
        s = (const float4*)((const char*)g_pehi + (size_t)ttile * 16384);
        d = (float4*)(dsm + R2);
#pragma unroll
        for (int i = 0; i < 2; i++) d[tid + i * HT] = s[tid + i * HT];
        s = (const float4*)((const char*)g_pelo + (size_t)ttile * 16384);
        d = (float4*)(dsm + R3);
#pragma unroll
        for (int i = 0; i < 2; i++) d[tid + i * HT] = s[tid + i * HT];
    }
    __syncthreads();

    uint32_t base = smem_u32(dsm);

    int grp = lane >> 3;
    int nrow = lq * 16 + ((grp & 2) << 2) + (lane & 7);
    int kh = grp & 1;

    // B fragments (W hi): nf=2, one ldsm4 per k
    uint32_t Bfh[2][4][2];
#pragma unroll
    for (int k = 0; k < 4; k++) {
        uint32_t off = sw128((uint32_t)nrow * 128 + k * 32 + kh * 16);
        uint32_t r[4];
        ldsm4(r, base + R0 + off);
        Bfh[0][k][0] = r[0]; Bfh[0][k][1] = r[1];
        Bfh[1][k][0] = r[2]; Bfh[1][k][1] = r[3];
    }

    int arow = lane & 15;
    int akh = lane >> 4;

    // bias values for this thread's 4 l columns
    float breg[4];
#pragma unroll
    for (int nf = 0; nf < 2; nf++) {
        breg[nf * 2 + 0] = db[l0 + lq * 16 + nf * 8 + (lane & 3) * 2 + 0];
        breg[nf * 2 + 1] = db[l0 + lq * 16 + nf * 8 + (lane & 3) * 2 + 1];
    }

    // c_init = PEhi@Whi + PElo@Whi + PEhi@Wlo + bias  (32 regs)
    float cinit[4][2][4];
#pragma unroll
    for (int tf = 0; tf < 4; tf++) {
        int row = tq * 64 + tf * 16 + arow;
        uint32_t Ah[4][4], Al[4][4];
#pragma unroll
        for (int k = 0; k < 4; k++) {
            uint32_t off = sw128((uint32_t)row * 128 + k * 32 + akh * 16);
            ldsm4(Ah[k], base + R2 + off);
            ldsm4(Al[k], base + R3 + off);
        }
        float c[2][4];
#pragma unroll
        for (int nf = 0; nf < 2; nf++)
#pragma unroll
            for (int q = 0; q < 4; q++) c[nf][q] = 0.f;

#pragma unroll
        for (int k = 0; k < 4; k++) {
            uint32_t off = sw128((uint32_t)nrow * 128 + k * 32 + kh * 16);
            uint32_t rl[4];
            ldsm4(rl, base + R1 + off);
            uint32_t Bl0[2] = {rl[0], rl[1]};
            uint32_t Bl1[2] = {rl[2], rl[3]};
            mma16816(c[0], Al[k], Bfh[0][k]);
            mma16816(c[1], Al[k], Bfh[1][k]);
            mma16816(c[0], Ah[k], Bl0);
            mma16816(c[1], Ah[k], Bl1);
            mma16816(c[0], Ah[k], Bfh[0][k]);
            mma16816(c[1], Ah[k], Bfh[1][k]);
        }
#pragma unroll
        for (int nf = 0; nf < 2; nf++) {
            cinit[tf][nf][0] = c[nf][0] + breg[nf * 2 + 0];
            cinit[tf][nf][1] = c[nf][1] + breg[nf * 2 + 1];
            cinit[tf][nf][2] = c[nf][2] + breg[nf * 2 + 0];
            cinit[tf][nf][3] = c[nf][3] + breg[nf * 2 + 1];
        }
    }
    __syncthreads();   // done reading R2/R3 (PE tiles)

    // load S(b=0) into R2
    const char* sbase0 = (const char*)g_sbf + (size_t)ttile * 16384;
    {
        const float4* s = (const float4*)sbase0;   // b=0
        float4* d = (float4*)(dsm + R2);
#pragma unroll
        for (int i = 0; i < 2; i++) d[tid + i * HT] = s[tid + i * HT];
    }
    __syncthreads();

    float* red = (float*)(dsm + R1);

    for (int b = 0; b < BB; b++) {
        int cur = b & 1;
        uint32_t sA = base + (cur ? R3 : R2);

        // prefetch next S tile into registers
        float4 creg[2];
        if (b + 1 < BB) {
            const float4* s =
                (const float4*)(sbase0 + (size_t)(b + 1) * NTILE * 16384);
#pragma unroll
            for (int j = 0; j < 2; j++) creg[j] = s[tid + j * HT];
        }

        float dacc[4];
#pragma unroll
        for (int j = 0; j < 4; j++) dacc[j] = 0.f;

#pragma unroll
        for (int tf = 0; tf < 4; tf++) {
            int row = tq * 64 + tf * 16 + arow;
            uint32_t Af[4][4];
#pragma unroll
            for (int k = 0; k < 4; k++)
                ldsm4(Af[k], sA + sw128((uint32_t)row * 128 + k * 32 + akh * 16));

            float c[2][4];
#pragma unroll
            for (int nf = 0; nf < 2; nf++)
#pragma unroll
                for (int q = 0; q < 4; q++) c[nf][q] = cinit[tf][nf][q];
#pragma unroll
            for (int k = 0; k < 4; k++)
#pragma unroll
                for (int nf = 0; nf < 2; nf++) mma16816(c[nf], Af[k], Bfh[nf][k]);

            // pair-merged sigmoid: c[nf][q] and c[nf][q+2] share the l column.
            // 2sig(a)+2sig(b) = 2*(2+ea+eb)/(1+ea+eb+ea*eb); one RCP per pair.
#pragma unroll
            for (int nf = 0; nf < 2; nf++) {
#pragma unroll
                for (int par = 0; par < 2; par++) {
                    float e0 = __expf(-c[nf][par]);
                    float e1 = __expf(-c[nf][par + 2]);
                    float s01 = e0 + e1;
                    float den = fmaf(e0, e1, 1.f + s01);
                    float num = 2.f + s01;
                    float r = __fdividef(num, den);
                    dacc[nf * 2 + par] += r + r;   // 2*sigma for both elements
                }
            }
        }

        // each slot saw 4 tf * 2 = 8 elements of 2*sigmoid
#pragma unroll
        for (int j = 0; j < 4; j++) dacc[j] -= 8.f;

        // reduce over the 8 lanes sharing lane&3
#pragma unroll
        for (int o = 4; o < 32; o <<= 1)
#pragma unroll
            for (int j = 0; j < 4; j++) dacc[j] += __shfl_xor_sync(~0u, dacc[j], o);

        // store prefetched S tile
        if (b + 1 < BB) {
            float4* d = (float4*)(dsm + (cur ? R2 : R3));
#pragma unroll
            for (int j = 0; j < 2; j++) d[tid + j * HT] = creg[j];
        }

        if (lane < 4) {
#pragma unroll
            for (int nf = 0; nf < 2; nf++) {
                red[tq * 128 + lq * 16 + nf * 8 + lane * 2 + 0] = dacc[nf * 2 + 0];
                red[tq * 128 + lq * 16 + nf * 8 + lane * 2 + 1] = dacc[nf * 2 + 1];
            }
        }
        __syncthreads();
        if (tid < 128)
            g_part2[((size_t)ttile * BB + b) * L + l0 + tid] = red[tid] + red[128 + tid];
        __syncthreads();
    }
}

// ---------------------------------------------------------------------------
// K4: Gaussian RBF warp — sums 32 ttile partials, truncated window |d| <= 6
// ---------------------------------------------------------------------------
__global__ __launch_bounds__(256) void warp_kernel(
    const float* __restrict__ x, float* __restrict__ out)
{
    int gid = blockIdx.x * 256 + threadIdx.x;   // = b*L + l
    int b = gid >> 12;
    int l = gid & (L - 1);

    float shift = 0.f;
#pragma unroll
    for (int tt = 0; tt < NTILE; tt++) shift += g_part2[(size_t)tt * BB * L + gid];

    float scale = (float)T / (float)L;
    float s = ((float)(l + 1) + shift) * scale;

    const float INV_AMP = (float)(1.0 / 1.772637204826652);
    float acc[8];
#pragma unroll
    for (int c = 0; c < 8; c++) acc[c] = 0.f;

    int lo = (int)ceilf(s - 6.0f);  if (lo < 1) lo = 1;
    int hi = (int)floorf(s + 6.0f); if (hi > T) hi = T;

    const float* xb = x + (size_t)b * T * C;
    for (int t = lo; t <= hi; t++) {
        float dd = (float)t - s;
        float wgt = expf(-dd * dd) * INV_AMP;
        const float4* xr = (const float4*)&xb[(t - 1) * C];
        float4 p0 = xr[0], p1 = xr[1];
        acc[0] += wgt * p0.x; acc[1] += wgt * p0.y;
        acc[2] += wgt * p0.z; acc[3] += wgt * p0.w;
        acc[4] += wgt * p1.x; acc[5] += wgt * p1.y;
        acc[6] += wgt * p1.z; acc[7] += wgt * p1.w;
    }
    float4* o = (float4*)&out[(size_t)gid * C];
    float4 r0 = {acc[0], acc[1], acc[2], acc[3]};
    float4 r1 = {acc[4], acc[5], acc[6], acc[7]};
    o[0] = r0; o[1] = r1;
}

// ---------------------------------------------------------------------------
extern "C" void kernel_launch(void* const* d_in, const int* in_sizes, int n_in,
                              void* d_out, int out_size)
{
    const float* x     = (const float*)d_in[0];
    const float* cw    = (const float*)d_in[1];
    const float* cb    = (const float*)d_in[2];
    const float* gamma = (const float*)d_in[3];
    const float* beta  = (const float*)d_in[4];
    const float* mean  = (const float*)d_in[5];
    const float* var   = (const float*)d_in[6];
    const float* dw    = (const float*)d_in[7];
    const float* db    = (const float*)d_in[8];
    float* out = (float*)d_out;

    cudaFuncSetAttribute(hmma_sig_kernel,
                         cudaFuncAttributeMaxDynamicSharedMemorySize, HMMA_SMEM);

    peprep_kernel<<<(F * T) / 256, 256>>>();
    wprep_kernel<<<(F * L) / 256, 256>>>(dw);
    conv_bn_kernel<<<dim3(T / CONV_TT, BB), 256>>>(x, cw, cb, gamma, beta, mean, var);
    softmax_kernel<<<BB * F, 256>>>();
    strans_kernel<<<dim3(NTILE, BB), 256>>>();
    hmma_sig_kernel<<<dim3(NTILE, NTILE), HT, HMMA_SMEM>>>(db);
    warp_kernel<<<(BB * L) / 256, 256>>>(x, out);
}

// round 15
// speedup vs baseline: 1.2786x; 1.0296x over previous
#include <cuda_runtime.h>
#include <cuda_fp16.h>
#include <math.h>
#include <stdint.h>

#define BB 16
#define T 4096
#define C 8
#define F 64
#define KW 11
#define PAD 5
#define L 4096
#define NTILE 32        // T/128 tiles (also L/128)

// ---- device scratch (no allocation allowed) ----
__device__ float g_h[BB * F * T];                              // conv+bn out [B][F][T]
__device__ __half g_sbf[(size_t)BB * NTILE * 128 * 64];        // S tiles [b][tile][t][f] SW128
__device__ __half g_wbf[NTILE * 128 * 64];                     // W hi tiles [ltile][l][f] SW128
__device__ __half g_wlo[NTILE * 128 * 64];                     // W lo tiles
__device__ __half g_pehi[NTILE * 128 * 64];                    // PE hi tiles [ttile][t][f] SW128
__device__ __half g_pelo[NTILE * 128 * 64];                    // PE lo tiles
__device__ float g_part2[(size_t)NTILE * BB * L];              // per-ttile partial shift sums

__device__ __forceinline__ uint32_t smem_u32(const void* p) {
    uint32_t a;
    asm("{ .reg .u64 t; cvta.to.shared.u64 t, %1; cvt.u32.u64 %0, t; }" : "=r"(a) : "l"(p));
    return a;
}
__host__ __device__ __forceinline__ uint32_t sw128(uint32_t off) {
    return off ^ ((off >> 3) & 0x70);
}

// ---------------------------------------------------------------------------
// K0a: PE -> fp16 hi/lo swizzled tiles [ttile][t][f]
// ---------------------------------------------------------------------------
__global__ void peprep_kernel() {
    int idx = blockIdx.x * 256 + threadIdx.x;      // F*T
    int f = idx >> 12, t = idx & (T - 1);
    float ts = powf(1e-4f, (float)(2 * (f >> 1)) / 64.0f);
    float ang = (float)t * ts;
    float v = (f & 1) ? cosf(ang) : sinf(ang);
    __half hi = __float2half(v);
    __half lo = __float2half(v - __half2float(hi));
    int tile = t >> 7, r = t & 127;
    uint32_t off = sw128(r * 128 + f * 2);
    *(__half*)((char*)g_pehi + (size_t)tile * 16384 + off) = hi;
    *(__half*)((char*)g_pelo + (size_t)tile * 16384 + off) = lo;
}

// ---------------------------------------------------------------------------
// K0b: W -> fp16 hi/lo swizzled tiles [ltile][l][f]
// ---------------------------------------------------------------------------
__global__ void wprep_kernel(const float* __restrict__ dw) {
    int idx = blockIdx.x * 256 + threadIdx.x;      // F*L
    int f = idx >> 12, l = idx & (L - 1);
    float v = dw[idx];
    __half hi = __float2half(v);
    __half lo = __float2half(v - __half2float(hi));
    int tile = l >> 7, r = l & 127;
    uint32_t off = sw128(r * 128 + f * 2);
    *(__half*)((char*)g_wbf + (size_t)tile * 16384 + off) = hi;
    *(__half*)((char*)g_wlo + (size_t)tile * 16384 + off) = lo;
}

// ---------------------------------------------------------------------------
// K1: Conv1D(SAME) + BatchNorm -> g_h [B][F][T]
// ---------------------------------------------------------------------------
#define CONV_TT 64
__global__ __launch_bounds__(256) void conv_bn_kernel(
    const float* __restrict__ x, const float* __restrict__ cw,
    const float* __restrict__ cb, const float* __restrict__ gamma,
    const float* __restrict__ beta, const float* __restrict__ mean,
    const float* __restrict__ var)
{
    __shared__ float xs[(CONV_TT + KW - 1) * 9];
    __shared__ float ws[KW * C * F];
    __shared__ float sc[F], bi[F];

    int b = blockIdx.y;
    int t0 = blockIdx.x * CONV_TT;
    int tid = threadIdx.x;

    for (int idx = tid; idx < (CONV_TT + KW - 1) * 9; idx += 256) {
        int i = idx / 9, c = idx % 9;
        float v = 0.f;
        int tg = t0 + i - PAD;
        if (c < 8 && tg >= 0 && tg < T) v = x[(b * T + tg) * C + c];
        xs[idx] = v;
    }
    for (int idx = tid; idx < KW * C * F; idx += 256) ws[idx] = cw[idx];
    if (tid < F) {
        float s = gamma[tid] / sqrtf(var[tid] + 1e-3f);
        sc[tid] = s;
        bi[tid] = (cb[tid] - mean[tid]) * s + beta[tid];
    }
    __syncthreads();

    int tx = tid & 31;
    int ty = tid >> 5;
    float acc0[8], acc1[8];
#pragma unroll
    for (int j = 0; j < 8; j++) { acc0[j] = 0.f; acc1[j] = 0.f; }

#pragma unroll
    for (int k = 0; k < KW; k++) {
#pragma unroll
        for (int c = 0; c < C; c++) {
            float x0 = xs[(tx * 2 + k) * 9 + c];
            float x1 = xs[(tx * 2 + 1 + k) * 9 + c];
            const float* wrow = &ws[(k * C + c) * F + ty * 8];
#pragma unroll
            for (int j = 0; j < 8; j++) {
                float w = wrow[j];
                acc0[j] += x0 * w;
                acc1[j] += x1 * w;
            }
        }
    }
#pragma unroll
    for (int j = 0; j < 8; j++) {
        int f = ty * 8 + j;
        float s = sc[f], o = bi[f];
        float2 v;
        v.x = acc0[j] * s + o;
        v.y = acc1[j] * s + o;
        *(float2*)&g_h[(size_t)(b * F + f) * T + t0 + tx * 2] = v;
    }
}

// ---------------------------------------------------------------------------
// K2: softmax over T, in-place fp32 into g_h
// ---------------------------------------------------------------------------
__global__ __launch_bounds__(256) void softmax_kernel()
{
    int r = blockIdx.x;            // b*F + f
    float* row = g_h + (size_t)r * T;
    int tid = threadIdx.x;

    float v[16];
#pragma unroll
    for (int i = 0; i < 16; i++) v[i] = row[i * 256 + tid];

    float m = v[0];
#pragma unroll
    for (int i = 1; i < 16; i++) m = fmaxf(m, v[i]);

    __shared__ float sm[8], ss[8];
#pragma unroll
    for (int o = 16; o > 0; o >>= 1) m = fmaxf(m, __shfl_xor_sync(~0u, m, o));
    if ((tid & 31) == 0) sm[tid >> 5] = m;
    __syncthreads();
    m = sm[0];
#pragma unroll
    for (int w = 1; w < 8; w++) m = fmaxf(m, sm[w]);

    float e[16];
    float lsum = 0.f;
#pragma unroll
    for (int i = 0; i < 16; i++) { e[i] = expf(v[i] - m); lsum += e[i]; }
#pragma unroll
    for (int o = 16; o > 0; o >>= 1) lsum += __shfl_xor_sync(~0u, lsum, o);
    if ((tid & 31) == 0) ss[tid >> 5] = lsum;
    __syncthreads();
    float total = 0.f;
#pragma unroll
    for (int w = 0; w < 8; w++) total += ss[w];

    float inv = 1.f / total;
#pragma unroll
    for (int i = 0; i < 16; i++) row[i * 256 + tid] = e[i] * inv;
}

// ---------------------------------------------------------------------------
// K2b: transpose S -> fp16 swizzled tiles g_sbf[b][tile][t][f]
// ---------------------------------------------------------------------------
__global__ __launch_bounds__(256) void strans_kernel()
{
    __shared__ float st[64][130];
    int b = blockIdx.y;
    int tile = blockIdx.x;
    int tid = threadIdx.x;
    const float* src = g_h + (size_t)b * F * T + tile * 128;

#pragma unroll
    for (int it = 0; it < 8; it++) {
        int e = tid + it * 256;        // f = e/32, t4 = e%32
        int f = e >> 5, t4 = e & 31;
        float4 v = *(const float4*)(src + (size_t)f * T + t4 * 4);
        st[f][t4 * 4 + 0] = v.x; st[f][t4 * 4 + 1] = v.y;
        st[f][t4 * 4 + 2] = v.z; st[f][t4 * 4 + 3] = v.w;
    }
    __syncthreads();

    char* dst = (char*)g_sbf + ((size_t)b * NTILE + tile) * 16384;
#pragma unroll
    for (int it = 0; it < 4; it++) {
        int e = tid + it * 256;        // t = e>>3, fc = e&7
        int t = e >> 3, fc = e & 7;
        __half tmp[8];
#pragma unroll
        for (int j = 0; j < 8; j++) tmp[j] = __float2half(st[fc * 8 + j][t]);
        *(float4*)(dst + sw128(t * 128 + fc * 16)) = *(float4*)tmp;
    }
}

// ---------------------------------------------------------------------------
// K3: fused HMMA with Taylor-linearized sigmoid.
// Prologue (per CTA, b-independent): z0 = PEhi@Whi+PElo@Whi+PEhi@Wlo+bias;
//   d0 = 2*sig(z0)-1 summed into base; s1 = 2*sig', s2 = sig'' stored in smem.
// Mainloop per b: delta = S@Whi (MMA); dacc += s1*delta + s2*delta^2 — no MUFU.
// 512 threads = 16 warps (2 tq x 8 lq), each warp nf=2.
// ---------------------------------------------------------------------------
__device__ __forceinline__ void ldsm4(uint32_t* r, uint32_t addr) {
    asm volatile("ldmatrix.sync.aligned.m8n8.x4.shared.b16 {%0,%1,%2,%3}, [%4];"
                 : "=r"(r[0]), "=r"(r[1]), "=r"(r[2]), "=r"(r[3]) : "r"(addr));
}
__device__ __forceinline__ void mma16816(float* c, const uint32_t* a, const uint32_t* b) {
    asm volatile(
        "mma.sync.aligned.m16n8k16.row.col.f32.f16.f16.f32 "
        "{%0,%1,%2,%3}, {%4,%5,%6,%7}, {%8,%9}, {%0,%1,%2,%3};"
        : "+f"(c[0]), "+f"(c[1]), "+f"(c[2]), "+f"(c[3])
        : "r"(a[0]), "r"(a[1]), "r"(a[2]), "r"(a[3]), "r"(b[0]), "r"(b[1]));
}

extern __shared__ __align__(16) unsigned char g_smem[];

// smem layout:
//  R0    [0,16K)        Whi tile
//  RS    [16K,144K)     sled: fp32 quads (s1,s2) per element, 16 slots x 512 x 16B
//  RB0   [144K,160K)    PEhi -> then S double-buffer 0
//  RB1   [160K,176K)    PElo -> then S double-buffer 1
//  RWLO  [176K,192K)    Wlo (prologue) -> reduce scratch (mainloop)
#define R0   0
#define RS   16384
#define RB0  147456
#define RB1  163840
#define RWLO 180224
#define HMMA_SMEM 196608
#define HT 512

__global__ __launch_bounds__(HT) void hmma_sig_kernel(const float* __restrict__ db)
{
    unsigned char* dsm = g_smem;
    int ltile = blockIdx.x, ttile = blockIdx.y;
    int l0 = ltile * 128;
    int tid = threadIdx.x, lane = tid & 31, w = tid >> 5;
    int tq = w >> 3, lq = w & 7;          // 2 t-groups x 8 l-groups (16 l each)

    // load Whi(R0), Wlo(RWLO), PEhi(RB0), PElo(RB1): each 1024 float4
    {
        const float4* s;
        float4* d;
        s = (const float4*)((const char*)g_wbf + (size_t)ltile * 16384);
        d = (float4*)(dsm + R0);
#pragma unroll
        for (int i = 0; i < 2; i++) d[tid + i * HT] = s[tid + i * HT];
        s = (const float4*)((const char*)g_wlo + (size_t)ltile * 16384);
        d = (float4*)(dsm + RWLO);
#pragma unroll
        for (int i = 0; i < 2; i++) d[tid + i * HT] = s[tid + i * HT];
        s = (const float4*)((const char*)g_pehi + (size_t)ttile * 16384);
        d = (float4*)(dsm + RB0);
#pragma unroll
        for (int i = 0; i < 2; i++) d[tid + i * HT] = s[tid + i * HT];
        s = (const float4*)((const char*)g_pelo + (size_t)ttile * 16384);
        d = (float4*)(dsm + RB1);
#pragma unroll
        for (int i = 0; i < 2; i++) d[tid + i * HT] = s[tid + i * HT];
    }
    __syncthreads();

    uint32_t base = smem_u32(dsm);

    int grp = lane >> 3;
    int nrow = lq * 16 + ((grp & 2) << 2) + (lane & 7);
    int kh = grp & 1;

    // B fragments (W hi): nf=2, one ldsm4 per k
    uint32_t Bfh[2][4][2];
#pragma unroll
    for (int k = 0; k < 4; k++) {
        uint32_t off = sw128((uint32_t)nrow * 128 + k * 32 + kh * 16);
        uint32_t r[4];
        ldsm4(r, base + R0 + off);
        Bfh[0][k][0] = r[0]; Bfh[0][k][1] = r[1];
        Bfh[1][k][0] = r[2]; Bfh[1][k][1] = r[3];
    }

    int arow = lane & 15;
    int akh = lane >> 4;

    // bias values for this thread's 4 l columns
    float breg[4];
#pragma unroll
    for (int nf = 0; nf < 2; nf++) {
        breg[nf * 2 + 0] = db[l0 + lq * 16 + nf * 8 + (lane & 3) * 2 + 0];
        breg[nf * 2 + 1] = db[l0 + lq * 16 + nf * 8 + (lane & 3) * 2 + 1];
    }

    // ---- prologue: z0 per element; base/d0 + Taylor coeffs into sled ----
    float baseacc[4];
#pragma unroll
    for (int j = 0; j < 4; j++) baseacc[j] = 0.f;

#pragma unroll
    for (int tf = 0; tf < 4; tf++) {
        int row = tq * 64 + tf * 16 + arow;
        uint32_t Ah[4][4], Al[4][4];
#pragma unroll
        for (int k = 0; k < 4; k++) {
            uint32_t off = sw128((uint32_t)row * 128 + k * 32 + akh * 16);
            ldsm4(Ah[k], base + RB0 + off);
            ldsm4(Al[k], base + RB1 + off);
        }
        float c[2][4];
#pragma unroll
        for (int nf = 0; nf < 2; nf++)
#pragma unroll
            for (int q = 0; q < 4; q++) c[nf][q] = 0.f;

#pragma unroll
        for (int k = 0; k < 4; k++) {
            uint32_t off = sw128((uint32_t)nrow * 128 + k * 32 + kh * 16);
            uint32_t rl[4];
            ldsm4(rl, base + RWLO + off);
            uint32_t Bl0[2] = {rl[0], rl[1]};
            uint32_t Bl1[2] = {rl[2], rl[3]};
            mma16816(c[0], Al[k], Bfh[0][k]);
            mma16816(c[1], Al[k], Bfh[1][k]);
            mma16816(c[0], Ah[k], Bl0);
            mma16816(c[1], Ah[k], Bl1);
            mma16816(c[0], Ah[k], Bfh[0][k]);
            mma16816(c[1], Ah[k], Bfh[1][k]);
        }

#pragma unroll
        for (int nf = 0; nf < 2; nf++) {
            float s1q[4], s2q[4];
#pragma unroll
            for (int q = 0; q < 4; q++) {
                float z = c[nf][q] + breg[nf * 2 + (q & 1)];
                float ee = __expf(-z);
                float inv = __fdividef(1.f, 1.f + ee);   // sigma
                float sp = ee * inv * inv;               // sigma'
                baseacc[nf * 2 + (q & 1)] += fmaf(2.f, inv, -1.f);  // d0 = 2*sig-1
                s1q[q] = sp + sp;                        // 2*sigma'
                s2q[q] = sp * fmaf(-2.f, inv, 1.f);      // sigma'' = sig'(1-2sig)
            }
            uint32_t slot = (uint32_t)(tf * 4 + nf * 2) * (HT * 16) + (uint32_t)tid * 16;
            *(float4*)(dsm + RS + slot) = *(float4*)s1q;
            *(float4*)(dsm + RS + slot + HT * 16) = *(float4*)s2q;
        }
    }
    __syncthreads();   // done reading RB0/RB1 (PE tiles) and RWLO (Wlo)

    // load S(b=0) into RB0
    const char* sbase0 = (const char*)g_sbf + (size_t)ttile * 16384;
    {
        const float4* s = (const float4*)sbase0;   // b=0
        float4* d = (float4*)(dsm + RB0);
#pragma unroll
        for (int i = 0; i < 2; i++) d[tid + i * HT] = s[tid + i * HT];
    }
    __syncthreads();

    float* red = (float*)(dsm + RWLO);

    for (int b = 0; b < BB; b++) {
        int cur = b & 1;
        uint32_t sA = base + (cur ? RB1 : RB0);

        // prefetch next S tile into registers
        float4 creg[2];
        if (b + 1 < BB) {
            const float4* s =
                (const float4*)(sbase0 + (size_t)(b + 1) * NTILE * 16384);
#pragma unroll
            for (int j = 0; j < 2; j++) creg[j] = s[tid + j * HT];
        }

        float dacc[4];
#pragma unroll
        for (int j = 0; j < 4; j++) dacc[j] = baseacc[j];

#pragma unroll
        for (int tf = 0; tf < 4; tf++) {
            int row = tq * 64 + tf * 16 + arow;
            uint32_t Af[4][4];
#pragma unroll
            for (int k = 0; k < 4; k++)
                ldsm4(Af[k], sA + sw128((uint32_t)row * 128 + k * 32 + akh * 16));

            float c[2][4];
#pragma unroll
            for (int nf = 0; nf < 2; nf++)
#pragma unroll
                for (int q = 0; q < 4; q++) c[nf][q] = 0.f;
#pragma unroll
            for (int k = 0; k < 4; k++)
#pragma unroll
                for (int nf = 0; nf < 2; nf++) mma16816(c[nf], Af[k], Bfh[nf][k]);

            // Taylor update: dacc += s1*delta + s2*delta^2 (pure FMA)
#pragma unroll
            for (int nf = 0; nf < 2; nf++) {
                uint32_t slot = (uint32_t)(tf * 4 + nf * 2) * (HT * 16) + (uint32_t)tid * 16;
                float4 s1q = *(const float4*)(dsm + RS + slot);
                float4 s2q = *(const float4*)(dsm + RS + slot + HT * 16);
                float dlt, u;
                dlt = c[nf][0]; u = fmaf(dlt, s2q.x, s1q.x);
                dacc[nf * 2 + 0] = fmaf(dlt, u, dacc[nf * 2 + 0]);
                dlt = c[nf][1]; u = fmaf(dlt, s2q.y, s1q.y);
                dacc[nf * 2 + 1] = fmaf(dlt, u, dacc[nf * 2 + 1]);
                dlt = c[nf][2]; u = fmaf(dlt, s2q.z, s1q.z);
                dacc[nf * 2 + 0] = fmaf(dlt, u, dacc[nf * 2 + 0]);
                dlt = c[nf][3]; u = fmaf(dlt, s2q.w, s1q.w);
                dacc[nf * 2 + 1] = fmaf(dlt, u, dacc[nf * 2 + 1]);
            }
        }

        // reduce over the 8 lanes sharing lane&3
#pragma unroll
        for (int o = 4; o < 32; o <<= 1)
#pragma unroll
            for (int j = 0; j < 4; j++) dacc[j] += __shfl_xor_sync(~0u, dacc[j], o);

        // store prefetched S tile
        if (b + 1 < BB) {
            float4* d = (float4*)(dsm + (cur ? RB0 : RB1));
#pragma unroll
            for (int j = 0; j < 2; j++) d[tid + j * HT] = creg[j];
        }

        if (lane < 4) {
#pragma unroll
            for (int nf = 0; nf < 2; nf++) {
                red[tq * 128 + lq * 16 + nf * 8 + lane * 2 + 0] = dacc[nf * 2 + 0];
                red[tq * 128 + lq * 16 + nf * 8 + lane * 2 + 1] = dacc[nf * 2 + 1];
            }
        }
        __syncthreads();
        if (tid < 128)
            g_part2[((size_t)ttile * BB + b) * L + l0 + tid] = red[tid] + red[128 + tid];
        __syncthreads();
    }
}

// ---------------------------------------------------------------------------
// K4: Gaussian RBF warp — sums 32 ttile partials, truncated window |d| <= 6
// ---------------------------------------------------------------------------
__global__ __launch_bounds__(256) void warp_kernel(
    const float* __restrict__ x, float* __restrict__ out)
{
    int gid = blockIdx.x * 256 + threadIdx.x;   // = b*L + l
    int b = gid >> 12;
    int l = gid & (L - 1);

    float shift = 0.f;
#pragma unroll
    for (int tt = 0; tt < NTILE; tt++) shift += g_part2[(size_t)tt * BB * L + gid];

    float scale = (float)T / (float)L;
    float s = ((float)(l + 1) + shift) * scale;

    const float INV_AMP = (float)(1.0 / 1.772637204826652);
    float acc[8];
#pragma unroll
    for (int c = 0; c < 8; c++) acc[c] = 0.f;

    int lo = (int)ceilf(s - 6.0f);  if (lo < 1) lo = 1;
    int hi = (int)floorf(s + 6.0f); if (hi > T) hi = T;

    const float* xb = x + (size_t)b * T * C;
    for (int t = lo; t <= hi; t++) {
        float dd = (float)t - s;
        float wgt = expf(-dd * dd) * INV_AMP;
        const float4* xr = (const float4*)&xb[(t - 1) * C];
        float4 p0 = xr[0], p1 = xr[1];
        acc[0] += wgt * p0.x; acc[1] += wgt * p0.y;
        acc[2] += wgt * p0.z; acc[3] += wgt * p0.w;
        acc[4] += wgt * p1.x; acc[5] += wgt * p1.y;
        acc[6] += wgt * p1.z; acc[7] += wgt * p1.w;
    }
    float4* o = (float4*)&out[(size_t)gid * C];
    float4 r0 = {acc[0], acc[1], acc[2], acc[3]};
    float4 r1 = {acc[4], acc[5], acc[6], acc[7]};
    o[0] = r0; o[1] = r1;
}

// ---------------------------------------------------------------------------
extern "C" void kernel_launch(void* const* d_in, const int* in_sizes, int n_in,
                              void* d_out, int out_size)
{
    const float* x     = (const float*)d_in[0];
    const float* cw    = (const float*)d_in[1];
    const float* cb    = (const float*)d_in[2];
    const float* gamma = (const float*)d_in[3];
    const float* beta  = (const float*)d_in[4];
    const float* mean  = (const float*)d_in[5];
    const float* var   = (const float*)d_in[6];
    const float* dw    = (const float*)d_in[7];
    const float* db    = (const float*)d_in[8];
    float* out = (float*)d_out;

    cudaFuncSetAttribute(hmma_sig_kernel,
                         cudaFuncAttributeMaxDynamicSharedMemorySize, HMMA_SMEM);

    peprep_kernel<<<(F * T) / 256, 256>>>();
    wprep_kernel<<<(F * L) / 256, 256>>>(dw);
    conv_bn_kernel<<<dim3(T / CONV_TT, BB), 256>>>(x, cw, cb, gamma, beta, mean, var);
    softmax_kernel<<<BB * F, 256>>>();
    strans_kernel<<<dim3(NTILE, BB), 256>>>();
    hmma_sig_kernel<<<dim3(NTILE, NTILE), HT, HMMA_SMEM>>>(db);
    warp_kernel<<<(BB * L) / 256, 256>>>(x, out);
}